// round 13
// baseline (speedup 1.0000x reference)
#include <cuda_runtime.h>
#include <cuda_fp16.h>
#include <cstdint>

#define L    4096
#define DM   768
#define NH   12
#define HD   64
#define ATTN_SCALE 0.125f   // folded into Q projection

// ---------------- scratch (no allocations allowed) ----------------
__device__ __align__(16) __half g_Xh[3][L * DM];
__device__ __align__(16) __half g_Wh[4][DM * DM];
__device__ __align__(16) __half g_Qh[L * DM];    // pre-scaled by 0.125
__device__ __align__(16) __half g_Kh[L * DM];
__device__ __align__(16) __half g_Vh[L * DM];
__device__ __align__(16) __half g_Ah[L * DM];

// =======================================================================
// helpers
// =======================================================================
__device__ __forceinline__ uint32_t f2h2(float lo, float hi) {
    __half2 h = __floats2half2_rn(lo, hi);
    return *(uint32_t*)&h;
}
__device__ __forceinline__ void mma_f16(float c[4], const uint32_t a[4], const uint32_t b[2]) {
    asm volatile(
        "mma.sync.aligned.m16n8k16.row.col.f32.f16.f16.f32 "
        "{%0,%1,%2,%3}, {%4,%5,%6,%7}, {%8,%9}, {%0,%1,%2,%3};"
        : "+f"(c[0]), "+f"(c[1]), "+f"(c[2]), "+f"(c[3])
        : "r"(a[0]), "r"(a[1]), "r"(a[2]), "r"(a[3]), "r"(b[0]), "r"(b[1]));
}
__device__ __forceinline__ void ldmx4t(uint32_t r[4], uint32_t addr) {
    asm volatile("ldmatrix.sync.aligned.m8n8.x4.trans.shared.b16 {%0,%1,%2,%3}, [%4];"
        : "=r"(r[0]), "=r"(r[1]), "=r"(r[2]), "=r"(r[3]) : "r"(addr));
}
__device__ __forceinline__ void cp16(uint32_t sdst, const void* gsrc) {
    asm volatile("cp.async.cg.shared.global [%0], [%1], 16;" :: "r"(sdst), "l"(gsrc));
}
#define CP_COMMIT() asm volatile("cp.async.commit_group;" ::: "memory")
#define CP_WAIT1()  asm volatile("cp.async.wait_group 1;" ::: "memory")
#define CP_WAIT0()  asm volatile("cp.async.wait_group 0;" ::: "memory")

// =======================================================================
// pack kernel: fp32 -> fp16 for X (3x) and W (4x)
// =======================================================================
#define X4 (L * DM / 4)
#define W4 (DM * DM / 4)
#define PACK_TOTAL (3 * X4 + 4 * W4)
#define PACK_BLOCKS (PACK_TOTAL / 256)

__global__ void __launch_bounds__(256)
pack_kernel(const float* __restrict__ xq, const float* __restrict__ xk, const float* __restrict__ xv,
            const float* __restrict__ wq, const float* __restrict__ wk, const float* __restrict__ wv,
            const float* __restrict__ wo)
{
    const int idx = blockIdx.x * 256 + threadIdx.x;
    float4 v;
    __half* dst;
    if (idx < 3 * X4) {
        const int z = idx / X4;
        const int r = idx - z * X4;
        const float* s = (z == 0) ? xq : (z == 1) ? xk : xv;
        v = ((const float4*)s)[r];
        dst = &g_Xh[z][r * 4];
    } else {
        const int t = idx - 3 * X4;
        const int z = t / W4;
        const int r = t - z * W4;
        const float* s = (z == 0) ? wq : (z == 1) ? wk : (z == 2) ? wv : wo;
        v = ((const float4*)s)[r];
        dst = &g_Wh[z][r * 4];
    }
    uint2 u = {f2h2(v.x, v.y), f2h2(v.z, v.w)};
    *(uint2*)dst = u;
}

// =======================================================================
// fp16 GEMM: 512 threads, CTA 128x128, warp tile 32x32 (4x4 warp grid),
// cp.async 3-stage ring, scalar LDS fragments. 2 CTAs/SM (32 warps).
// =======================================================================
#define BKH 64
#define SSH 72
#define NT (DM / BKH)                          // 12
#define STAGEH ((128 + 128) * SSH)             // A 128 rows + B 128 rows
#define GEMM_SMEM (3 * STAGEH * 2)             // 110592 B

__device__ __forceinline__ void stage_tiles(uint32_t sbase,
                                            const __half* __restrict__ A, int i0,
                                            const __half* __restrict__ B, int j0,
                                            int kt, int tid)
{
#pragma unroll
    for (int i = 0; i < 2; ++i) {
        const int f = tid + i * 512;
        const int r = f >> 3, c = f & 7;
        cp16(sbase + (uint32_t)(r * SSH + c * 8) * 2,
             A + (size_t)(i0 + r) * DM + kt * BKH + c * 8);
    }
#pragma unroll
    for (int i = 0; i < 2; ++i) {
        const int f = tid + i * 512;
        const int r = f >> 3, c = f & 7;
        cp16(sbase + (uint32_t)((128 + r) * SSH + c * 8) * 2,
             B + (size_t)(j0 + r) * DM + kt * BKH + c * 8);
    }
}

template <bool OUTF32>
__device__ __forceinline__ void gemm_h(const __half* __restrict__ A,
                                       const __half* __restrict__ B,
                                       const float* __restrict__ bias,
                                       void* __restrict__ Cout,
                                       int i0, int j0, float oscale)
{
    extern __shared__ __half smh[];
    const uint32_t sb = (uint32_t)__cvta_generic_to_shared(smh);

    const int tid  = threadIdx.x;
    const int wid  = tid >> 5;
    const int lane = tid & 31;
    const int gq   = lane >> 2;
    const int tg   = lane & 3;
    const int wm0  = (wid & 3) * 32;           // warp M base
    const int wn0  = (wid >> 2) * 32;          // warp N base

    float acc[2][4][4] = {};

    stage_tiles(sb, A, i0, B, j0, 0, tid);
    CP_COMMIT();
    stage_tiles(sb + STAGEH * 2, A, i0, B, j0, 1, tid);
    CP_COMMIT();

    int buf = 0;
    for (int kt = 0; kt < NT; ++kt) {
        if (kt == NT - 1) { CP_WAIT0(); } else { CP_WAIT1(); }
        __syncthreads();

        const __half* Ac = smh + buf * STAGEH;
        const __half* Bc = Ac + 128 * SSH;
#pragma unroll
        for (int kk = 0; kk < BKH; kk += 16) {
            uint32_t af[2][4], bf[4][2];
#pragma unroll
            for (int mt = 0; mt < 2; ++mt) {
                const int r = wm0 + mt * 16 + gq;
                af[mt][0] = *(const uint32_t*)&Ac[(r    ) * SSH + kk + 2 * tg    ];
                af[mt][1] = *(const uint32_t*)&Ac[(r + 8) * SSH + kk + 2 * tg    ];
                af[mt][2] = *(const uint32_t*)&Ac[(r    ) * SSH + kk + 2 * tg + 8];
                af[mt][3] = *(const uint32_t*)&Ac[(r + 8) * SSH + kk + 2 * tg + 8];
            }
#pragma unroll
            for (int nt = 0; nt < 4; ++nt) {
                const int n = wn0 + nt * 8 + gq;
                bf[nt][0] = *(const uint32_t*)&Bc[n * SSH + kk + 2 * tg    ];
                bf[nt][1] = *(const uint32_t*)&Bc[n * SSH + kk + 2 * tg + 8];
            }
#pragma unroll
            for (int mt = 0; mt < 2; ++mt)
#pragma unroll
                for (int nt = 0; nt < 4; ++nt)
                    mma_f16(acc[mt][nt], af[mt], bf[nt]);
        }

        if (kt + 2 < NT) {
            const int nb = (buf + 2 >= 3) ? buf - 1 : buf + 2;
            stage_tiles(sb + (uint32_t)nb * STAGEH * 2, A, i0, B, j0, kt + 2, tid);
            CP_COMMIT();
        }
        buf = (buf + 1 == 3) ? 0 : buf + 1;
    }

#pragma unroll
    for (int nt = 0; nt < 4; ++nt) {
        const int col = j0 + wn0 + nt * 8 + 2 * tg;
        const float2 bb = *(const float2*)&bias[col];
#pragma unroll
        for (int mt = 0; mt < 2; ++mt) {
            const int r = i0 + wm0 + mt * 16 + gq;
            if (OUTF32) {
                float* C = (float*)Cout;
                float2 s0 = {acc[mt][nt][0] + bb.x, acc[mt][nt][1] + bb.y};
                float2 s1 = {acc[mt][nt][2] + bb.x, acc[mt][nt][3] + bb.y};
                *(float2*)&C[(size_t)r * DM + col] = s0;
                *(float2*)&C[(size_t)(r + 8) * DM + col] = s1;
            } else {
                __half* C = (__half*)Cout;
                uint32_t h0 = f2h2((acc[mt][nt][0] + bb.x) * oscale,
                                   (acc[mt][nt][1] + bb.y) * oscale);
                uint32_t h1 = f2h2((acc[mt][nt][2] + bb.x) * oscale,
                                   (acc[mt][nt][3] + bb.y) * oscale);
                *(uint32_t*)&C[(size_t)r * DM + col] = h0;
                *(uint32_t*)&C[(size_t)(r + 8) * DM + col] = h1;
            }
        }
    }
}

__global__ void __launch_bounds__(512, 2)
qkv_proj_kernel(const float* __restrict__ bq, const float* __restrict__ bk,
                const float* __restrict__ bv)
{
    const int z = blockIdx.z;
    const float* Bb = (z == 0) ? bq : (z == 1) ? bk : bv;
    __half* dst     = (z == 0) ? g_Qh : (z == 1) ? g_Kh : g_Vh;
    const float sc  = (z == 0) ? ATTN_SCALE : 1.0f;
    gemm_h<false>(g_Xh[z], g_Wh[z], Bb, dst, blockIdx.x * 128, blockIdx.y * 128, sc);
}

__global__ void __launch_bounds__(512, 2)
out_proj_kernel(const float* __restrict__ bo, float* __restrict__ out)
{
    gemm_h<true>(g_Ah, g_Wh[3], bo, out, blockIdx.x * 128, blockIdx.y * 128, 1.0f);
}

// =======================================================================
// flash-style sliding-window attention (R12, unchanged)
// =======================================================================
#define AQKH 72
#define AOFF_QS 0
#define AOFF_KS 18432
#define AOFF_VS 55296
#define ATT_SMEM_BYTES (AOFF_VS + 256 * AQKH * 2)   // 92160

__global__ void __launch_bounds__(256, 2)
attn_kernel()
{
    extern __shared__ char smc[];
    __half* Qs = (__half*)(smc + AOFF_QS);
    __half* Ks = (__half*)(smc + AOFF_KS);

    const int tid  = threadIdx.x;
    const int q0   = blockIdx.x * 128;
    const int h    = blockIdx.y;
    const int c0   = h * HD;
    const int wid  = tid >> 5;
    const int lane = tid & 31;
    const int gq   = lane >> 2;
    const int tg   = lane & 3;

    const uint32_t sbase = (uint32_t)__cvta_generic_to_shared(smc);

    {
        const uint32_t sQ = sbase + AOFF_QS;
        const uint32_t sK = sbase + AOFF_KS;
        const uint32_t sV = sbase + AOFF_VS;
#pragma unroll
        for (int i = 0; i < 4; ++i) {
            const int f = tid + i * 256;
            const int q = f >> 3, c = f & 7;
            cp16(sQ + (uint32_t)(q * AQKH + c * 8) * 2,
                 g_Qh + (size_t)(q0 + q) * DM + c0 + c * 8);
        }
#pragma unroll
        for (int i = 0; i < 8; ++i) {
            const int f = tid + i * 256;
            const int j = f >> 3, c = f & 7;
            const int jg = min(max(q0 - 64 + j, 0), L - 1);
            cp16(sK + (uint32_t)(j * AQKH + c * 8) * 2,
                 g_Kh + (size_t)jg * DM + c0 + c * 8);
            cp16(sV + (uint32_t)(j * AQKH + c * 8) * 2,
                 g_Vh + (size_t)jg * DM + c0 + c * 8);
        }
        CP_COMMIT();
    }
    CP_WAIT0();
    __syncthreads();

    const int wm  = wid * 16;
    const int iq0 = q0 + wm + gq;
    const int iq1 = iq0 + 8;
    const int lo0 = max(iq0 - 64, 0), hi0 = min(iq0 + 64, L - 1);
    const int lo1 = max(iq1 - 64, 0), hi1 = min(iq1 + 64, L - 1);

    float oacc[8][4] = {};
    float m0 = -1e30f, m1 = -1e30f;
    float l0 = 0.f,    l1 = 0.f;

    const int jbase0 = (wid >> 2) * 64;
    const int vrow = lane & 15;
    const int vcol = (lane >> 4) * 8;

    for (int cb = 0; cb < 3; ++cb) {
        const int jb = jbase0 + cb * 64;

        float sc[8][4] = {};
#pragma unroll
        for (int kk = 0; kk < 64; kk += 16) {
            uint32_t a[4];
            a[0] = *(const uint32_t*)&Qs[(wm + gq    ) * AQKH + kk + 2 * tg    ];
            a[1] = *(const uint32_t*)&Qs[(wm + gq + 8) * AQKH + kk + 2 * tg    ];
            a[2] = *(const uint32_t*)&Qs[(wm + gq    ) * AQKH + kk + 2 * tg + 8];
            a[3] = *(const uint32_t*)&Qs[(wm + gq + 8) * AQKH + kk + 2 * tg + 8];
#pragma unroll
            for (int nt = 0; nt < 8; ++nt) {
                const int n = jb + nt * 8 + gq;
                uint32_t b[2];
                b[0] = *(const uint32_t*)&Ks[n * AQKH + kk + 2 * tg    ];
                b[1] = *(const uint32_t*)&Ks[n * AQKH + kk + 2 * tg + 8];
                mma_f16(sc[nt], a, b);
            }
        }

        float mn0 = m0, mn1 = m1;
#pragma unroll
        for (int nt = 0; nt < 8; ++nt) {
            const int jg0 = q0 - 64 + jb + nt * 8 + 2 * tg;
#pragma unroll
            for (int e = 0; e < 4; ++e) {
                const int jg = jg0 + (e & 1);
                float s = sc[nt][e];
                if (e < 2) {
                    s = (jg >= lo0 && jg <= hi0) ? s : -1e30f;
                    mn0 = fmaxf(mn0, s);
                } else {
                    s = (jg >= lo1 && jg <= hi1) ? s : -1e30f;
                    mn1 = fmaxf(mn1, s);
                }
                sc[nt][e] = s;
            }
        }
        mn0 = fmaxf(mn0, __shfl_xor_sync(0xffffffffu, mn0, 1));
        mn0 = fmaxf(mn0, __shfl_xor_sync(0xffffffffu, mn0, 2));
        mn1 = fmaxf(mn1, __shfl_xor_sync(0xffffffffu, mn1, 1));
        mn1 = fmaxf(mn1, __shfl_xor_sync(0xffffffffu, mn1, 2));
        const float al0 = __expf(m0 - mn0);
        const float al1 = __expf(m1 - mn1);
        m0 = mn0; m1 = mn1;

        uint32_t ph[8][2];
        float cs0 = 0.f, cs1 = 0.f;
#pragma unroll
        for (int nt = 0; nt < 8; ++nt) {
            const float p0 = __expf(sc[nt][0] - m0);
            const float p1 = __expf(sc[nt][1] - m0);
            const float p2 = __expf(sc[nt][2] - m1);
            const float p3 = __expf(sc[nt][3] - m1);
            ph[nt][0] = f2h2(p0, p1);
            ph[nt][1] = f2h2(p2, p3);
            cs0 += p0 + p1;
            cs1 += p2 + p3;
        }
        cs0 += __shfl_xor_sync(0xffffffffu, cs0, 1);
        cs0 += __shfl_xor_sync(0xffffffffu, cs0, 2);
        cs1 += __shfl_xor_sync(0xffffffffu, cs1, 1);
        cs1 += __shfl_xor_sync(0xffffffffu, cs1, 2);
        l0 = l0 * al0 + cs0;
        l1 = l1 * al1 + cs1;

#pragma unroll
        for (int dnt = 0; dnt < 8; ++dnt) {
            oacc[dnt][0] *= al0; oacc[dnt][1] *= al0;
            oacc[dnt][2] *= al1; oacc[dnt][3] *= al1;
        }

#pragma unroll
        for (int t = 0; t < 4; ++t) {
            uint32_t a[4] = { ph[2 * t][0], ph[2 * t][1],
                              ph[2 * t + 1][0], ph[2 * t + 1][1] };
#pragma unroll
            for (int dt = 0; dt < 4; ++dt) {
                uint32_t bt[4];
                ldmx4t(bt, sbase + AOFF_VS +
                       (uint32_t)((jb + t * 16 + vrow) * AQKH + dt * 16 + vcol) * 2);
                mma_f16(oacc[2 * dt    ], a, &bt[0]);
                mma_f16(oacc[2 * dt + 1], a, &bt[2]);
            }
        }
    }

    const float inv0 = 1.f / l0;
    const float inv1 = 1.f / l1;
#pragma unroll
    for (int dnt = 0; dnt < 8; ++dnt) {
        const int d = dnt * 8 + 2 * tg;
        const uint32_t h0 = f2h2(oacc[dnt][0] * inv0, oacc[dnt][1] * inv0);
        const uint32_t h1 = f2h2(oacc[dnt][2] * inv1, oacc[dnt][3] * inv1);
        *(uint32_t*)&g_Ah[(size_t)iq0 * DM + c0 + d] = h0;
        *(uint32_t*)&g_Ah[(size_t)iq1 * DM + c0 + d] = h1;
    }
}

// ---------------- launch ----------------
extern "C" void kernel_launch(void* const* d_in, const int* in_sizes, int n_in,
                              void* d_out, int out_size)
{
    const float* q  = (const float*)d_in[0];
    const float* k  = (const float*)d_in[1];
    const float* v  = (const float*)d_in[2];
    const float* Wq = (const float*)d_in[3];
    const float* bq = (const float*)d_in[4];
    const float* Wk = (const float*)d_in[5];
    const float* bk = (const float*)d_in[6];
    const float* Wv = (const float*)d_in[7];
    const float* bv = (const float*)d_in[8];
    const float* Wo = (const float*)d_in[9];
    const float* bo = (const float*)d_in[10];
    float* out = (float*)d_out;

    cudaFuncSetAttribute(qkv_proj_kernel,
                         cudaFuncAttributeMaxDynamicSharedMemorySize, GEMM_SMEM);
    cudaFuncSetAttribute(out_proj_kernel,
                         cudaFuncAttributeMaxDynamicSharedMemorySize, GEMM_SMEM);
    cudaFuncSetAttribute(attn_kernel,
                         cudaFuncAttributeMaxDynamicSharedMemorySize, ATT_SMEM_BYTES);

    pack_kernel<<<PACK_BLOCKS, 256>>>(q, k, v, Wq, Wk, Wv, Wo);
    qkv_proj_kernel<<<dim3(L / 128, DM / 128, 3), 512, GEMM_SMEM>>>(bq, bk, bv);
    attn_kernel<<<dim3(L / 128, NH), 256, ATT_SMEM_BYTES>>>();
    out_proj_kernel<<<dim3(L / 128, DM / 128), 512, GEMM_SMEM>>>(bo, out);
}

// round 14
// speedup vs baseline: 1.0349x; 1.0349x over previous
#include <cuda_runtime.h>
#include <cuda_fp16.h>
#include <cstdint>

#define L    4096
#define DM   768
#define NH   12
#define HD   64
#define ATTN_SCALE 0.125f   // folded into Q projection

// ---------------- scratch (no allocations allowed) ----------------
__device__ __align__(16) __half g_Xh[3][L * DM];
__device__ __align__(16) __half g_Wh[4][DM * DM];
__device__ __align__(16) __half g_Qh[L * DM];    // pre-scaled by 0.125
__device__ __align__(16) __half g_Kh[L * DM];
__device__ __align__(16) __half g_Vh[L * DM];
__device__ __align__(16) __half g_Ah[L * DM];

// =======================================================================
// helpers
// =======================================================================
__device__ __forceinline__ uint32_t f2h2(float lo, float hi) {
    __half2 h = __floats2half2_rn(lo, hi);
    return *(uint32_t*)&h;
}
__device__ __forceinline__ void mma_f16(float c[4], const uint32_t a[4], const uint32_t b[2]) {
    asm volatile(
        "mma.sync.aligned.m16n8k16.row.col.f32.f16.f16.f32 "
        "{%0,%1,%2,%3}, {%4,%5,%6,%7}, {%8,%9}, {%0,%1,%2,%3};"
        : "+f"(c[0]), "+f"(c[1]), "+f"(c[2]), "+f"(c[3])
        : "r"(a[0]), "r"(a[1]), "r"(a[2]), "r"(a[3]), "r"(b[0]), "r"(b[1]));
}
__device__ __forceinline__ void ldmx4t(uint32_t r[4], uint32_t addr) {
    asm volatile("ldmatrix.sync.aligned.m8n8.x4.trans.shared.b16 {%0,%1,%2,%3}, [%4];"
        : "=r"(r[0]), "=r"(r[1]), "=r"(r[2]), "=r"(r[3]) : "r"(addr));
}
__device__ __forceinline__ void cp16(uint32_t sdst, const void* gsrc) {
    asm volatile("cp.async.cg.shared.global [%0], [%1], 16;" :: "r"(sdst), "l"(gsrc));
}
#define CP_COMMIT() asm volatile("cp.async.commit_group;" ::: "memory")
#define CP_WAIT1()  asm volatile("cp.async.wait_group 1;" ::: "memory")
#define CP_WAIT0()  asm volatile("cp.async.wait_group 0;" ::: "memory")

// =======================================================================
// pack kernel: fp32 -> fp16 for X (3x) and W (4x)
// =======================================================================
#define X4 (L * DM / 4)
#define W4 (DM * DM / 4)
#define PACK_TOTAL (3 * X4 + 4 * W4)
#define PACK_BLOCKS (PACK_TOTAL / 256)

__global__ void __launch_bounds__(256)
pack_kernel(const float* __restrict__ xq, const float* __restrict__ xk, const float* __restrict__ xv,
            const float* __restrict__ wq, const float* __restrict__ wk, const float* __restrict__ wv,
            const float* __restrict__ wo)
{
    const int idx = blockIdx.x * 256 + threadIdx.x;
    float4 v;
    __half* dst;
    if (idx < 3 * X4) {
        const int z = idx / X4;
        const int r = idx - z * X4;
        const float* s = (z == 0) ? xq : (z == 1) ? xk : xv;
        v = ((const float4*)s)[r];
        dst = &g_Xh[z][r * 4];
    } else {
        const int t = idx - 3 * X4;
        const int z = t / W4;
        const int r = t - z * W4;
        const float* s = (z == 0) ? wq : (z == 1) ? wk : (z == 2) ? wv : wo;
        v = ((const float4*)s)[r];
        dst = &g_Wh[z][r * 4];
    }
    uint2 u = {f2h2(v.x, v.y), f2h2(v.z, v.w)};
    *(uint2*)dst = u;
}

// =======================================================================
// fp16 GEMM: cp.async ring + scalar LDS fragments, 256 threads.
// MROWS=128: 8 warps 4x2, warp tile 32x64, 3-stage ring (R12 proven).
// MROWS=64 : 8 warps 4x2, warp tile 16x64, 2-stage ring (3 CTAs/SM).
// =======================================================================
#define BKH 64
#define SSH 72
#define NT (DM / BKH)                          // 12

#define QKV_STAGEH ((128 + 128) * SSH)
#define OUT_STAGEH ((64 + 128) * SSH)
#define QKV_SMEM (3 * QKV_STAGEH * 2)          // 110592 B
#define OUT_SMEM (2 * OUT_STAGEH * 2)          // 55296 B

template <int MROWS>
__device__ __forceinline__ void stage_tiles(uint32_t sbase,
                                            const __half* __restrict__ A, int i0,
                                            const __half* __restrict__ B, int j0,
                                            int kt, int tid)
{
#pragma unroll
    for (int i = 0; i < MROWS * 8 / 256; ++i) {
        const int f = tid + i * 256;
        const int r = f >> 3, c = f & 7;
        cp16(sbase + (uint32_t)(r * SSH + c * 8) * 2,
             A + (size_t)(i0 + r) * DM + kt * BKH + c * 8);
    }
#pragma unroll
    for (int i = 0; i < 4; ++i) {
        const int f = tid + i * 256;
        const int r = f >> 3, c = f & 7;
        cp16(sbase + (uint32_t)((MROWS + r) * SSH + c * 8) * 2,
             B + (size_t)(j0 + r) * DM + kt * BKH + c * 8);
    }
}

template <int MROWS>
__device__ __forceinline__ void compute_ktile(float acc[][8][4],
                                              const __half* __restrict__ Ac,
                                              int wm0, int wn0, int gq, int tg)
{
    constexpr int MT = MROWS / 64;
    const __half* Bc = Ac + MROWS * SSH;
#pragma unroll
    for (int kk = 0; kk < BKH; kk += 16) {
        uint32_t af[MT][4], bf[8][2];
#pragma unroll
        for (int mt = 0; mt < MT; ++mt) {
            const int r = wm0 + mt * 16 + gq;
            af[mt][0] = *(const uint32_t*)&Ac[(r    ) * SSH + kk + 2 * tg    ];
            af[mt][1] = *(const uint32_t*)&Ac[(r + 8) * SSH + kk + 2 * tg    ];
            af[mt][2] = *(const uint32_t*)&Ac[(r    ) * SSH + kk + 2 * tg + 8];
            af[mt][3] = *(const uint32_t*)&Ac[(r + 8) * SSH + kk + 2 * tg + 8];
        }
#pragma unroll
        for (int nt = 0; nt < 8; ++nt) {
            const int n = wn0 + nt * 8 + gq;
            bf[nt][0] = *(const uint32_t*)&Bc[n * SSH + kk + 2 * tg    ];
            bf[nt][1] = *(const uint32_t*)&Bc[n * SSH + kk + 2 * tg + 8];
        }
#pragma unroll
        for (int mt = 0; mt < MT; ++mt)
#pragma unroll
            for (int nt = 0; nt < 8; ++nt)
                mma_f16(acc[mt][nt], af[mt], bf[nt]);
    }
}

template <int MROWS, bool OUTF32>
__device__ __forceinline__ void gemm_epilogue(float acc[][8][4],
                                              const float* __restrict__ bias,
                                              void* __restrict__ Cout,
                                              int i0, int j0, float oscale,
                                              int wm0, int wn0, int gq, int tg)
{
    constexpr int MT = MROWS / 64;
#pragma unroll
    for (int nt = 0; nt < 8; ++nt) {
        const int col = j0 + wn0 + nt * 8 + 2 * tg;
        const float2 bb = *(const float2*)&bias[col];
#pragma unroll
        for (int mt = 0; mt < MT; ++mt) {
            const int r = i0 + wm0 + mt * 16 + gq;
            if (OUTF32) {
                float* C = (float*)Cout;
                float2 s0 = {acc[mt][nt][0] + bb.x, acc[mt][nt][1] + bb.y};
                float2 s1 = {acc[mt][nt][2] + bb.x, acc[mt][nt][3] + bb.y};
                *(float2*)&C[(size_t)r * DM + col] = s0;
                *(float2*)&C[(size_t)(r + 8) * DM + col] = s1;
            } else {
                __half* C = (__half*)Cout;
                uint32_t h0 = f2h2((acc[mt][nt][0] + bb.x) * oscale,
                                   (acc[mt][nt][1] + bb.y) * oscale);
                uint32_t h1 = f2h2((acc[mt][nt][2] + bb.x) * oscale,
                                   (acc[mt][nt][3] + bb.y) * oscale);
                *(uint32_t*)&C[(size_t)r * DM + col] = h0;
                *(uint32_t*)&C[(size_t)(r + 8) * DM + col] = h1;
            }
        }
    }
}

__global__ void __launch_bounds__(256, 2)
qkv_proj_kernel(const float* __restrict__ bq, const float* __restrict__ bk,
                const float* __restrict__ bv)
{
    const int z = blockIdx.z;
    const float* bias = (z == 0) ? bq : (z == 1) ? bk : bv;
    __half* dst       = (z == 0) ? g_Qh : (z == 1) ? g_Kh : g_Vh;
    const float sc    = (z == 0) ? ATTN_SCALE : 1.0f;
    const __half* A   = g_Xh[z];
    const __half* B   = g_Wh[z];
    const int i0 = blockIdx.x * 128;
    const int j0 = blockIdx.y * 128;

    extern __shared__ __half smh[];
    const uint32_t sb = (uint32_t)__cvta_generic_to_shared(smh);

    const int tid  = threadIdx.x;
    const int wid  = tid >> 5;
    const int lane = tid & 31;
    const int gq   = lane >> 2;
    const int tg   = lane & 3;
    const int wm0  = (wid & 3) * 32;
    const int wn0  = (wid >> 2) * 64;

    float acc[2][8][4] = {};

    stage_tiles<128>(sb, A, i0, B, j0, 0, tid);
    CP_COMMIT();
    stage_tiles<128>(sb + QKV_STAGEH * 2, A, i0, B, j0, 1, tid);
    CP_COMMIT();

    int buf = 0;
    for (int kt = 0; kt < NT; ++kt) {
        if (kt == NT - 1) { CP_WAIT0(); } else { CP_WAIT1(); }
        __syncthreads();
        compute_ktile<128>(acc, smh + buf * QKV_STAGEH, wm0, wn0, gq, tg);
        if (kt + 2 < NT) {
            const int nb = (buf + 2 >= 3) ? buf - 1 : buf + 2;
            stage_tiles<128>(sb + (uint32_t)nb * QKV_STAGEH * 2, A, i0, B, j0, kt + 2, tid);
            CP_COMMIT();
        }
        buf = (buf + 1 == 3) ? 0 : buf + 1;
    }
    gemm_epilogue<128, false>(acc, bias, dst, i0, j0, sc, wm0, wn0, gq, tg);
}

__global__ void __launch_bounds__(256, 3)
out_proj_kernel(const float* __restrict__ bo, float* __restrict__ out)
{
    const int i0 = blockIdx.x * 64;
    const int j0 = blockIdx.y * 128;
    const __half* A = g_Ah;
    const __half* B = g_Wh[3];

    extern __shared__ __half smh[];
    const uint32_t sb = (uint32_t)__cvta_generic_to_shared(smh);

    const int tid  = threadIdx.x;
    const int wid  = tid >> 5;
    const int lane = tid & 31;
    const int gq   = lane >> 2;
    const int tg   = lane & 3;
    const int wm0  = (wid & 3) * 16;
    const int wn0  = (wid >> 2) * 64;

    float acc[1][8][4] = {};

    // 2-stage ring, one barrier: prefetch kt+1 AFTER compute kt (still async).
    stage_tiles<64>(sb, A, i0, B, j0, 0, tid);
    CP_COMMIT();

    for (int kt = 0; kt < NT; ++kt) {
        CP_WAIT0();
        __syncthreads();
        const int buf = kt & 1;
        compute_ktile<64>(acc, smh + buf * OUT_STAGEH, wm0, wn0, gq, tg);
        if (kt + 1 < NT) {
            stage_tiles<64>(sb + (uint32_t)(buf ^ 1) * OUT_STAGEH * 2, A, i0, B, j0, kt + 1, tid);
            CP_COMMIT();
        }
    }
    gemm_epilogue<64, true>(acc, bo, out, i0, j0, 1.0f, wm0, wn0, gq, tg);
}

// =======================================================================
// flash-style sliding-window attention (R12, unchanged)
// =======================================================================
#define AQKH 72
#define AOFF_QS 0
#define AOFF_KS 18432
#define AOFF_VS 55296
#define ATT_SMEM_BYTES (AOFF_VS + 256 * AQKH * 2)   // 92160

__global__ void __launch_bounds__(256, 2)
attn_kernel()
{
    extern __shared__ char smc[];
    __half* Qs = (__half*)(smc + AOFF_QS);
    __half* Ks = (__half*)(smc + AOFF_KS);

    const int tid  = threadIdx.x;
    const int q0   = blockIdx.x * 128;
    const int h    = blockIdx.y;
    const int c0   = h * HD;
    const int wid  = tid >> 5;
    const int lane = tid & 31;
    const int gq   = lane >> 2;
    const int tg   = lane & 3;

    const uint32_t sbase = (uint32_t)__cvta_generic_to_shared(smc);

    {
        const uint32_t sQ = sbase + AOFF_QS;
        const uint32_t sK = sbase + AOFF_KS;
        const uint32_t sV = sbase + AOFF_VS;
#pragma unroll
        for (int i = 0; i < 4; ++i) {
            const int f = tid + i * 256;
            const int q = f >> 3, c = f & 7;
            cp16(sQ + (uint32_t)(q * AQKH + c * 8) * 2,
                 g_Qh + (size_t)(q0 + q) * DM + c0 + c * 8);
        }
#pragma unroll
        for (int i = 0; i < 8; ++i) {
            const int f = tid + i * 256;
            const int j = f >> 3, c = f & 7;
            const int jg = min(max(q0 - 64 + j, 0), L - 1);
            cp16(sK + (uint32_t)(j * AQKH + c * 8) * 2,
                 g_Kh + (size_t)jg * DM + c0 + c * 8);
            cp16(sV + (uint32_t)(j * AQKH + c * 8) * 2,
                 g_Vh + (size_t)jg * DM + c0 + c * 8);
        }
        CP_COMMIT();
    }
    CP_WAIT0();
    __syncthreads();

    const int wm  = wid * 16;
    const int iq0 = q0 + wm + gq;
    const int iq1 = iq0 + 8;
    const int lo0 = max(iq0 - 64, 0), hi0 = min(iq0 + 64, L - 1);
    const int lo1 = max(iq1 - 64, 0), hi1 = min(iq1 + 64, L - 1);

    float oacc[8][4] = {};
    float m0 = -1e30f, m1 = -1e30f;
    float l0 = 0.f,    l1 = 0.f;

    const int jbase0 = (wid >> 2) * 64;
    const int vrow = lane & 15;
    const int vcol = (lane >> 4) * 8;

    for (int cb = 0; cb < 3; ++cb) {
        const int jb = jbase0 + cb * 64;

        float sc[8][4] = {};
#pragma unroll
        for (int kk = 0; kk < 64; kk += 16) {
            uint32_t a[4];
            a[0] = *(const uint32_t*)&Qs[(wm + gq    ) * AQKH + kk + 2 * tg    ];
            a[1] = *(const uint32_t*)&Qs[(wm + gq + 8) * AQKH + kk + 2 * tg    ];
            a[2] = *(const uint32_t*)&Qs[(wm + gq    ) * AQKH + kk + 2 * tg + 8];
            a[3] = *(const uint32_t*)&Qs[(wm + gq + 8) * AQKH + kk + 2 * tg + 8];
#pragma unroll
            for (int nt = 0; nt < 8; ++nt) {
                const int n = jb + nt * 8 + gq;
                uint32_t b[2];
                b[0] = *(const uint32_t*)&Ks[n * AQKH + kk + 2 * tg    ];
                b[1] = *(const uint32_t*)&Ks[n * AQKH + kk + 2 * tg + 8];
                mma_f16(sc[nt], a, b);
            }
        }

        float mn0 = m0, mn1 = m1;
#pragma unroll
        for (int nt = 0; nt < 8; ++nt) {
            const int jg0 = q0 - 64 + jb + nt * 8 + 2 * tg;
#pragma unroll
            for (int e = 0; e < 4; ++e) {
                const int jg = jg0 + (e & 1);
                float s = sc[nt][e];
                if (e < 2) {
                    s = (jg >= lo0 && jg <= hi0) ? s : -1e30f;
                    mn0 = fmaxf(mn0, s);
                } else {
                    s = (jg >= lo1 && jg <= hi1) ? s : -1e30f;
                    mn1 = fmaxf(mn1, s);
                }
                sc[nt][e] = s;
            }
        }
        mn0 = fmaxf(mn0, __shfl_xor_sync(0xffffffffu, mn0, 1));
        mn0 = fmaxf(mn0, __shfl_xor_sync(0xffffffffu, mn0, 2));
        mn1 = fmaxf(mn1, __shfl_xor_sync(0xffffffffu, mn1, 1));
        mn1 = fmaxf(mn1, __shfl_xor_sync(0xffffffffu, mn1, 2));
        const float al0 = __expf(m0 - mn0);
        const float al1 = __expf(m1 - mn1);
        m0 = mn0; m1 = mn1;

        uint32_t ph[8][2];
        float cs0 = 0.f, cs1 = 0.f;
#pragma unroll
        for (int nt = 0; nt < 8; ++nt) {
            const float p0 = __expf(sc[nt][0] - m0);
            const float p1 = __expf(sc[nt][1] - m0);
            const float p2 = __expf(sc[nt][2] - m1);
            const float p3 = __expf(sc[nt][3] - m1);
            ph[nt][0] = f2h2(p0, p1);
            ph[nt][1] = f2h2(p2, p3);
            cs0 += p0 + p1;
            cs1 += p2 + p3;
        }
        cs0 += __shfl_xor_sync(0xffffffffu, cs0, 1);
        cs0 += __shfl_xor_sync(0xffffffffu, cs0, 2);
        cs1 += __shfl_xor_sync(0xffffffffu, cs1, 1);
        cs1 += __shfl_xor_sync(0xffffffffu, cs1, 2);
        l0 = l0 * al0 + cs0;
        l1 = l1 * al1 + cs1;

#pragma unroll
        for (int dnt = 0; dnt < 8; ++dnt) {
            oacc[dnt][0] *= al0; oacc[dnt][1] *= al0;
            oacc[dnt][2] *= al1; oacc[dnt][3] *= al1;
        }

#pragma unroll
        for (int t = 0; t < 4; ++t) {
            uint32_t a[4] = { ph[2 * t][0], ph[2 * t][1],
                              ph[2 * t + 1][0], ph[2 * t + 1][1] };
#pragma unroll
            for (int dt = 0; dt < 4; ++dt) {
                uint32_t bt[4];
                ldmx4t(bt, sbase + AOFF_VS +
                       (uint32_t)((jb + t * 16 + vrow) * AQKH + dt * 16 + vcol) * 2);
                mma_f16(oacc[2 * dt    ], a, &bt[0]);
                mma_f16(oacc[2 * dt + 1], a, &bt[2]);
            }
        }
    }

    const float inv0 = 1.f / l0;
    const float inv1 = 1.f / l1;
#pragma unroll
    for (int dnt = 0; dnt < 8; ++dnt) {
        const int d = dnt * 8 + 2 * tg;
        const uint32_t h0 = f2h2(oacc[dnt][0] * inv0, oacc[dnt][1] * inv0);
        const uint32_t h1 = f2h2(oacc[dnt][2] * inv1, oacc[dnt][3] * inv1);
        *(uint32_t*)&g_Ah[(size_t)iq0 * DM + c0 + d] = h0;
        *(uint32_t*)&g_Ah[(size_t)iq1 * DM + c0 + d] = h1;
    }
}

// ---------------- launch ----------------
extern "C" void kernel_launch(void* const* d_in, const int* in_sizes, int n_in,
                              void* d_out, int out_size)
{
    const float* q  = (const float*)d_in[0];
    const float* k  = (const float*)d_in[1];
    const float* v  = (const float*)d_in[2];
    const float* Wq = (const float*)d_in[3];
    const float* bq = (const float*)d_in[4];
    const float* Wk = (const float*)d_in[5];
    const float* bk = (const float*)d_in[6];
    const float* Wv = (const float*)d_in[7];
    const float* bv = (const float*)d_in[8];
    const float* Wo = (const float*)d_in[9];
    const float* bo = (const float*)d_in[10];
    float* out = (float*)d_out;

    cudaFuncSetAttribute(qkv_proj_kernel,
                         cudaFuncAttributeMaxDynamicSharedMemorySize, QKV_SMEM);
    cudaFuncSetAttribute(out_proj_kernel,
                         cudaFuncAttributeMaxDynamicSharedMemorySize, OUT_SMEM);
    cudaFuncSetAttribute(attn_kernel,
                         cudaFuncAttributeMaxDynamicSharedMemorySize, ATT_SMEM_BYTES);

    pack_kernel<<<PACK_BLOCKS, 256>>>(q, k, v, Wq, Wk, Wv, Wo);
    qkv_proj_kernel<<<dim3(L / 128, DM / 128, 3), 256, QKV_SMEM>>>(bq, bk, bv);
    attn_kernel<<<dim3(L / 128, NH), 256, ATT_SMEM_BYTES>>>();
    out_proj_kernel<<<dim3(L / 64, DM / 128), 256, OUT_SMEM>>>(bo, out);
}

// round 15
// speedup vs baseline: 1.0364x; 1.0014x over previous
#include <cuda_runtime.h>
#include <cuda_fp16.h>
#include <cstdint>

#define L    4096
#define DM   768
#define NH   12
#define HD   64
#define ATTN_SCALE 0.125f   // folded into Q projection

// ---------------- scratch (no allocations allowed) ----------------
__device__ __align__(16) __half g_Xh[3][L * DM];
__device__ __align__(16) __half g_Wh[4][DM * DM];
__device__ __align__(16) __half g_Qh[L * DM];    // pre-scaled by 0.125
__device__ __align__(16) __half g_Kh[L * DM];
__device__ __align__(16) __half g_Vh[L * DM];
__device__ __align__(16) __half g_Ah[L * DM];

// =======================================================================
// helpers
// =======================================================================
__device__ __forceinline__ uint32_t f2h2(float lo, float hi) {
    __half2 h = __floats2half2_rn(lo, hi);
    return *(uint32_t*)&h;
}
__device__ __forceinline__ void mma_f16(float c[4], const uint32_t a[4], const uint32_t b[2]) {
    asm volatile(
        "mma.sync.aligned.m16n8k16.row.col.f32.f16.f16.f32 "
        "{%0,%1,%2,%3}, {%4,%5,%6,%7}, {%8,%9}, {%0,%1,%2,%3};"
        : "+f"(c[0]), "+f"(c[1]), "+f"(c[2]), "+f"(c[3])
        : "r"(a[0]), "r"(a[1]), "r"(a[2]), "r"(a[3]), "r"(b[0]), "r"(b[1]));
}
__device__ __forceinline__ void ldmx4t(uint32_t r[4], uint32_t addr) {
    asm volatile("ldmatrix.sync.aligned.m8n8.x4.trans.shared.b16 {%0,%1,%2,%3}, [%4];"
        : "=r"(r[0]), "=r"(r[1]), "=r"(r[2]), "=r"(r[3]) : "r"(addr));
}
__device__ __forceinline__ void cp16(uint32_t sdst, const void* gsrc) {
    asm volatile("cp.async.cg.shared.global [%0], [%1], 16;" :: "r"(sdst), "l"(gsrc));
}
#define CP_COMMIT() asm volatile("cp.async.commit_group;" ::: "memory")
#define CP_WAIT1()  asm volatile("cp.async.wait_group 1;" ::: "memory")
#define CP_WAIT0()  asm volatile("cp.async.wait_group 0;" ::: "memory")

// =======================================================================
// pack kernel: fp32 -> fp16 for X (3x) and W (4x)
// =======================================================================
#define X4 (L * DM / 4)
#define W4 (DM * DM / 4)
#define PACK_TOTAL (3 * X4 + 4 * W4)
#define PACK_BLOCKS (PACK_TOTAL / 256)

__global__ void __launch_bounds__(256)
pack_kernel(const float* __restrict__ xq, const float* __restrict__ xk, const float* __restrict__ xv,
            const float* __restrict__ wq, const float* __restrict__ wk, const float* __restrict__ wv,
            const float* __restrict__ wo)
{
    const int idx = blockIdx.x * 256 + threadIdx.x;
    float4 v;
    __half* dst;
    if (idx < 3 * X4) {
        const int z = idx / X4;
        const int r = idx - z * X4;
        const float* s = (z == 0) ? xq : (z == 1) ? xk : xv;
        v = ((const float4*)s)[r];
        dst = &g_Xh[z][r * 4];
    } else {
        const int t = idx - 3 * X4;
        const int z = t / W4;
        const int r = t - z * W4;
        const float* s = (z == 0) ? wq : (z == 1) ? wk : (z == 2) ? wv : wo;
        v = ((const float4*)s)[r];
        dst = &g_Wh[z][r * 4];
    }
    uint2 u = {f2h2(v.x, v.y), f2h2(v.z, v.w)};
    *(uint2*)dst = u;
}

// =======================================================================
// common GEMM pieces
// =======================================================================
#define BKH 64
#define SSH 72
#define NT (DM / BKH)                          // 12

// qkv: CTA tile 256x128, warp tile 64x64 (8 warps 4x2), 3-stage ring
#define QKV_STAGEH ((256 + 128) * SSH)
#define QKV_SMEM (3 * QKV_STAGEH * 2)          // 165888 B

// out_proj: CTA tile 64x128, warp tile 16x64, 2-stage ring (R14 proven)
#define OUT_STAGEH ((64 + 128) * SSH)
#define OUT_SMEM (2 * OUT_STAGEH * 2)          // 55296 B

template <int MROWS>
__device__ __forceinline__ void stage_tiles(uint32_t sbase,
                                            const __half* __restrict__ A, int i0,
                                            const __half* __restrict__ B, int j0,
                                            int kt, int tid)
{
#pragma unroll
    for (int i = 0; i < MROWS * 8 / 256; ++i) {
        const int f = tid + i * 256;
        const int r = f >> 3, c = f & 7;
        cp16(sbase + (uint32_t)(r * SSH + c * 8) * 2,
             A + (size_t)(i0 + r) * DM + kt * BKH + c * 8);
    }
#pragma unroll
    for (int i = 0; i < 4; ++i) {
        const int f = tid + i * 256;
        const int r = f >> 3, c = f & 7;
        cp16(sbase + (uint32_t)((MROWS + r) * SSH + c * 8) * 2,
             B + (size_t)(j0 + r) * DM + kt * BKH + c * 8);
    }
}

// =======================================================================
// qkv: fat warp tile 64x64 -> LDS/MMA = 1.0
// =======================================================================
__global__ void __launch_bounds__(256, 1)
qkv_proj_kernel(const float* __restrict__ bq, const float* __restrict__ bk,
                const float* __restrict__ bv)
{
    const int z = blockIdx.z;
    const float* bias = (z == 0) ? bq : (z == 1) ? bk : bv;
    __half* dst       = (z == 0) ? g_Qh : (z == 1) ? g_Kh : g_Vh;
    const float sc    = (z == 0) ? ATTN_SCALE : 1.0f;
    const __half* A   = g_Xh[z];
    const __half* B   = g_Wh[z];
    const int i0 = blockIdx.x * 256;
    const int j0 = blockIdx.y * 128;

    extern __shared__ __half smh[];
    const uint32_t sb = (uint32_t)__cvta_generic_to_shared(smh);

    const int tid  = threadIdx.x;
    const int wid  = tid >> 5;
    const int lane = tid & 31;
    const int gq   = lane >> 2;
    const int tg   = lane & 3;
    const int wm0  = (wid & 3) * 64;           // warp M base (0..192)
    const int wn0  = (wid >> 2) * 64;          // warp N base (0,64)

    float acc[4][8][4] = {};

    stage_tiles<256>(sb, A, i0, B, j0, 0, tid);
    CP_COMMIT();
    stage_tiles<256>(sb + QKV_STAGEH * 2, A, i0, B, j0, 1, tid);
    CP_COMMIT();

    int buf = 0;
    for (int kt = 0; kt < NT; ++kt) {
        if (kt == NT - 1) { CP_WAIT0(); } else { CP_WAIT1(); }
        __syncthreads();

        const __half* Ac = smh + buf * QKV_STAGEH;
        const __half* Bc = Ac + 256 * SSH;
#pragma unroll
        for (int kk = 0; kk < BKH; kk += 16) {
            uint32_t af[4][4], bf[8][2];
#pragma unroll
            for (int mt = 0; mt < 4; ++mt) {
                const int r = wm0 + mt * 16 + gq;
                af[mt][0] = *(const uint32_t*)&Ac[(r    ) * SSH + kk + 2 * tg    ];
                af[mt][1] = *(const uint32_t*)&Ac[(r + 8) * SSH + kk + 2 * tg    ];
                af[mt][2] = *(const uint32_t*)&Ac[(r    ) * SSH + kk + 2 * tg + 8];
                af[mt][3] = *(const uint32_t*)&Ac[(r + 8) * SSH + kk + 2 * tg + 8];
            }
#pragma unroll
            for (int nt = 0; nt < 8; ++nt) {
                const int n = wn0 + nt * 8 + gq;
                bf[nt][0] = *(const uint32_t*)&Bc[n * SSH + kk + 2 * tg    ];
                bf[nt][1] = *(const uint32_t*)&Bc[n * SSH + kk + 2 * tg + 8];
            }
#pragma unroll
            for (int mt = 0; mt < 4; ++mt)
#pragma unroll
                for (int nt = 0; nt < 8; ++nt)
                    mma_f16(acc[mt][nt], af[mt], bf[nt]);
        }

        if (kt + 2 < NT) {
            const int nb = (buf + 2 >= 3) ? buf - 1 : buf + 2;
            stage_tiles<256>(sb + (uint32_t)nb * QKV_STAGEH * 2, A, i0, B, j0, kt + 2, tid);
            CP_COMMIT();
        }
        buf = (buf + 1 == 3) ? 0 : buf + 1;
    }

#pragma unroll
    for (int nt = 0; nt < 8; ++nt) {
        const int col = j0 + wn0 + nt * 8 + 2 * tg;
        const float2 bb = *(const float2*)&bias[col];
#pragma unroll
        for (int mt = 0; mt < 4; ++mt) {
            const int r = i0 + wm0 + mt * 16 + gq;
            uint32_t h0 = f2h2((acc[mt][nt][0] + bb.x) * sc,
                               (acc[mt][nt][1] + bb.y) * sc);
            uint32_t h1 = f2h2((acc[mt][nt][2] + bb.x) * sc,
                               (acc[mt][nt][3] + bb.y) * sc);
            *(uint32_t*)&dst[(size_t)r * DM + col] = h0;
            *(uint32_t*)&dst[(size_t)(r + 8) * DM + col] = h1;
        }
    }
}

// =======================================================================
// out_proj (R14 proven): 64x128 tile, 2-stage ring, (256,3)
// =======================================================================
__global__ void __launch_bounds__(256, 3)
out_proj_kernel(const float* __restrict__ bo, float* __restrict__ out)
{
    const int i0 = blockIdx.x * 64;
    const int j0 = blockIdx.y * 128;
    const __half* A = g_Ah;
    const __half* B = g_Wh[3];

    extern __shared__ __half smh[];
    const uint32_t sb = (uint32_t)__cvta_generic_to_shared(smh);

    const int tid  = threadIdx.x;
    const int wid  = tid >> 5;
    const int lane = tid & 31;
    const int gq   = lane >> 2;
    const int tg   = lane & 3;
    const int wm0  = (wid & 3) * 16;
    const int wn0  = (wid >> 2) * 64;

    float acc[8][4] = {};

    stage_tiles<64>(sb, A, i0, B, j0, 0, tid);
    CP_COMMIT();

    for (int kt = 0; kt < NT; ++kt) {
        CP_WAIT0();
        __syncthreads();
        const int buf = kt & 1;
        const __half* Ac = smh + buf * OUT_STAGEH;
        const __half* Bc = Ac + 64 * SSH;
#pragma unroll
        for (int kk = 0; kk < BKH; kk += 16) {
            uint32_t af[4], bf[8][2];
            const int r = wm0 + gq;
            af[0] = *(const uint32_t*)&Ac[(r    ) * SSH + kk + 2 * tg    ];
            af[1] = *(const uint32_t*)&Ac[(r + 8) * SSH + kk + 2 * tg    ];
            af[2] = *(const uint32_t*)&Ac[(r    ) * SSH + kk + 2 * tg + 8];
            af[3] = *(const uint32_t*)&Ac[(r + 8) * SSH + kk + 2 * tg + 8];
#pragma unroll
            for (int nt = 0; nt < 8; ++nt) {
                const int n = wn0 + nt * 8 + gq;
                bf[nt][0] = *(const uint32_t*)&Bc[n * SSH + kk + 2 * tg    ];
                bf[nt][1] = *(const uint32_t*)&Bc[n * SSH + kk + 2 * tg + 8];
            }
#pragma unroll
            for (int nt = 0; nt < 8; ++nt)
                mma_f16(acc[nt], af, bf[nt]);
        }
        if (kt + 1 < NT) {
            stage_tiles<64>(sb + (uint32_t)(buf ^ 1) * OUT_STAGEH * 2, A, i0, B, j0, kt + 1, tid);
            CP_COMMIT();
        }
    }

#pragma unroll
    for (int nt = 0; nt < 8; ++nt) {
        const int col = j0 + wn0 + nt * 8 + 2 * tg;
        const float2 bb = *(const float2*)&bo[col];
        const int r = i0 + wm0 + gq;
        float2 s0 = {acc[nt][0] + bb.x, acc[nt][1] + bb.y};
        float2 s1 = {acc[nt][2] + bb.x, acc[nt][3] + bb.y};
        *(float2*)&out[(size_t)r * DM + col] = s0;
        *(float2*)&out[(size_t)(r + 8) * DM + col] = s1;
    }
}

// =======================================================================
// flash-style sliding-window attention (R12, unchanged)
// =======================================================================
#define AQKH 72
#define AOFF_QS 0
#define AOFF_KS 18432
#define AOFF_VS 55296
#define ATT_SMEM_BYTES (AOFF_VS + 256 * AQKH * 2)   // 92160

__global__ void __launch_bounds__(256, 2)
attn_kernel()
{
    extern __shared__ char smc[];
    __half* Qs = (__half*)(smc + AOFF_QS);
    __half* Ks = (__half*)(smc + AOFF_KS);

    const int tid  = threadIdx.x;
    const int q0   = blockIdx.x * 128;
    const int h    = blockIdx.y;
    const int c0   = h * HD;
    const int wid  = tid >> 5;
    const int lane = tid & 31;
    const int gq   = lane >> 2;
    const int tg   = lane & 3;

    const uint32_t sbase = (uint32_t)__cvta_generic_to_shared(smc);

    {
        const uint32_t sQ = sbase + AOFF_QS;
        const uint32_t sK = sbase + AOFF_KS;
        const uint32_t sV = sbase + AOFF_VS;
#pragma unroll
        for (int i = 0; i < 4; ++i) {
            const int f = tid + i * 256;
            const int q = f >> 3, c = f & 7;
            cp16(sQ + (uint32_t)(q * AQKH + c * 8) * 2,
                 g_Qh + (size_t)(q0 + q) * DM + c0 + c * 8);
        }
#pragma unroll
        for (int i = 0; i < 8; ++i) {
            const int f = tid + i * 256;
            const int j = f >> 3, c = f & 7;
            const int jg = min(max(q0 - 64 + j, 0), L - 1);
            cp16(sK + (uint32_t)(j * AQKH + c * 8) * 2,
                 g_Kh + (size_t)jg * DM + c0 + c * 8);
            cp16(sV + (uint32_t)(j * AQKH + c * 8) * 2,
                 g_Vh + (size_t)jg * DM + c0 + c * 8);
        }
        CP_COMMIT();
    }
    CP_WAIT0();
    __syncthreads();

    const int wm  = wid * 16;
    const int iq0 = q0 + wm + gq;
    const int iq1 = iq0 + 8;
    const int lo0 = max(iq0 - 64, 0), hi0 = min(iq0 + 64, L - 1);
    const int lo1 = max(iq1 - 64, 0), hi1 = min(iq1 + 64, L - 1);

    float oacc[8][4] = {};
    float m0 = -1e30f, m1 = -1e30f;
    float l0 = 0.f,    l1 = 0.f;

    const int jbase0 = (wid >> 2) * 64;
    const int vrow = lane & 15;
    const int vcol = (lane >> 4) * 8;

    for (int cb = 0; cb < 3; ++cb) {
        const int jb = jbase0 + cb * 64;

        float sc[8][4] = {};
#pragma unroll
        for (int kk = 0; kk < 64; kk += 16) {
            uint32_t a[4];
            a[0] = *(const uint32_t*)&Qs[(wm + gq    ) * AQKH + kk + 2 * tg    ];
            a[1] = *(const uint32_t*)&Qs[(wm + gq + 8) * AQKH + kk + 2 * tg    ];
            a[2] = *(const uint32_t*)&Qs[(wm + gq    ) * AQKH + kk + 2 * tg + 8];
            a[3] = *(const uint32_t*)&Qs[(wm + gq + 8) * AQKH + kk + 2 * tg + 8];
#pragma unroll
            for (int nt = 0; nt < 8; ++nt) {
                const int n = jb + nt * 8 + gq;
                uint32_t b[2];
                b[0] = *(const uint32_t*)&Ks[n * AQKH + kk + 2 * tg    ];
                b[1] = *(const uint32_t*)&Ks[n * AQKH + kk + 2 * tg + 8];
                mma_f16(sc[nt], a, b);
            }
        }

        float mn0 = m0, mn1 = m1;
#pragma unroll
        for (int nt = 0; nt < 8; ++nt) {
            const int jg0 = q0 - 64 + jb + nt * 8 + 2 * tg;
#pragma unroll
            for (int e = 0; e < 4; ++e) {
                const int jg = jg0 + (e & 1);
                float s = sc[nt][e];
                if (e < 2) {
                    s = (jg >= lo0 && jg <= hi0) ? s : -1e30f;
                    mn0 = fmaxf(mn0, s);
                } else {
                    s = (jg >= lo1 && jg <= hi1) ? s : -1e30f;
                    mn1 = fmaxf(mn1, s);
                }
                sc[nt][e] = s;
            }
        }
        mn0 = fmaxf(mn0, __shfl_xor_sync(0xffffffffu, mn0, 1));
        mn0 = fmaxf(mn0, __shfl_xor_sync(0xffffffffu, mn0, 2));
        mn1 = fmaxf(mn1, __shfl_xor_sync(0xffffffffu, mn1, 1));
        mn1 = fmaxf(mn1, __shfl_xor_sync(0xffffffffu, mn1, 2));
        const float al0 = __expf(m0 - mn0);
        const float al1 = __expf(m1 - mn1);
        m0 = mn0; m1 = mn1;

        uint32_t ph[8][2];
        float cs0 = 0.f, cs1 = 0.f;
#pragma unroll
        for (int nt = 0; nt < 8; ++nt) {
            const float p0 = __expf(sc[nt][0] - m0);
            const float p1 = __expf(sc[nt][1] - m0);
            const float p2 = __expf(sc[nt][2] - m1);
            const float p3 = __expf(sc[nt][3] - m1);
            ph[nt][0] = f2h2(p0, p1);
            ph[nt][1] = f2h2(p2, p3);
            cs0 += p0 + p1;
            cs1 += p2 + p3;
        }
        cs0 += __shfl_xor_sync(0xffffffffu, cs0, 1);
        cs0 += __shfl_xor_sync(0xffffffffu, cs0, 2);
        cs1 += __shfl_xor_sync(0xffffffffu, cs1, 1);
        cs1 += __shfl_xor_sync(0xffffffffu, cs1, 2);
        l0 = l0 * al0 + cs0;
        l1 = l1 * al1 + cs1;

#pragma unroll
        for (int dnt = 0; dnt < 8; ++dnt) {
            oacc[dnt][0] *= al0; oacc[dnt][1] *= al0;
            oacc[dnt][2] *= al1; oacc[dnt][3] *= al1;
        }

#pragma unroll
        for (int t = 0; t < 4; ++t) {
            uint32_t a[4] = { ph[2 * t][0], ph[2 * t][1],
                              ph[2 * t + 1][0], ph[2 * t + 1][1] };
#pragma unroll
            for (int dt = 0; dt < 4; ++dt) {
                uint32_t bt[4];
                ldmx4t(bt, sbase + AOFF_VS +
                       (uint32_t)((jb + t * 16 + vrow) * AQKH + dt * 16 + vcol) * 2);
                mma_f16(oacc[2 * dt    ], a, &bt[0]);
                mma_f16(oacc[2 * dt + 1], a, &bt[2]);
            }
        }
    }

    const float inv0 = 1.f / l0;
    const float inv1 = 1.f / l1;
#pragma unroll
    for (int dnt = 0; dnt < 8; ++dnt) {
        const int d = dnt * 8 + 2 * tg;
        const uint32_t h0 = f2h2(oacc[dnt][0] * inv0, oacc[dnt][1] * inv0);
        const uint32_t h1 = f2h2(oacc[dnt][2] * inv1, oacc[dnt][3] * inv1);
        *(uint32_t*)&g_Ah[(size_t)iq0 * DM + c0 + d] = h0;
        *(uint32_t*)&g_Ah[(size_t)iq1 * DM + c0 + d] = h1;
    }
}

// ---------------- launch ----------------
extern "C" void kernel_launch(void* const* d_in, const int* in_sizes, int n_in,
                              void* d_out, int out_size)
{
    const float* q  = (const float*)d_in[0];
    const float* k  = (const float*)d_in[1];
    const float* v  = (const float*)d_in[2];
    const float* Wq = (const float*)d_in[3];
    const float* bq = (const float*)d_in[4];
    const float* Wk = (const float*)d_in[5];
    const float* bk = (const float*)d_in[6];
    const float* Wv = (const float*)d_in[7];
    const float* bv = (const float*)d_in[8];
    const float* Wo = (const float*)d_in[9];
    const float* bo = (const float*)d_in[10];
    float* out = (float*)d_out;

    cudaFuncSetAttribute(qkv_proj_kernel,
                         cudaFuncAttributeMaxDynamicSharedMemorySize, QKV_SMEM);
    cudaFuncSetAttribute(out_proj_kernel,
                         cudaFuncAttributeMaxDynamicSharedMemorySize, OUT_SMEM);
    cudaFuncSetAttribute(attn_kernel,
                         cudaFuncAttributeMaxDynamicSharedMemorySize, ATT_SMEM_BYTES);

    pack_kernel<<<PACK_BLOCKS, 256>>>(q, k, v, Wq, Wk, Wv, Wo);
    qkv_proj_kernel<<<dim3(L / 256, DM / 128, 3), 256, QKV_SMEM>>>(bq, bk, bv);
    attn_kernel<<<dim3(L / 128, NH), 256, ATT_SMEM_BYTES>>>();
    out_proj_kernel<<<dim3(L / 64, DM / 128), 256, OUT_SMEM>>>(bo, out);
}

// round 16
// speedup vs baseline: 1.0962x; 1.0577x over previous
#include <cuda_runtime.h>
#include <cuda_fp16.h>
#include <cstdint>

#define L    4096
#define DM   768
#define NH   12
#define HD   64
#define ATTN_SCALE 0.125f   // folded into Q projection

// ---------------- scratch (no allocations allowed) ----------------
__device__ __align__(16) __half g_Xh[3][L * DM];
__device__ __align__(16) __half g_Wh[4][DM * DM];
__device__ __align__(16) __half g_Qh[L * DM];    // pre-scaled by 0.125
__device__ __align__(16) __half g_Kh[L * DM];
__device__ __align__(16) __half g_Vh[L * DM];
__device__ __align__(16) __half g_Ah[L * DM];

// =======================================================================
// helpers
// =======================================================================
__device__ __forceinline__ uint32_t f2h2(float lo, float hi) {
    __half2 h = __floats2half2_rn(lo, hi);
    return *(uint32_t*)&h;
}
__device__ __forceinline__ void mma_f16(float c[4], const uint32_t a[4], const uint32_t b[2]) {
    asm volatile(
        "mma.sync.aligned.m16n8k16.row.col.f32.f16.f16.f32 "
        "{%0,%1,%2,%3}, {%4,%5,%6,%7}, {%8,%9}, {%0,%1,%2,%3};"
        : "+f"(c[0]), "+f"(c[1]), "+f"(c[2]), "+f"(c[3])
        : "r"(a[0]), "r"(a[1]), "r"(a[2]), "r"(a[3]), "r"(b[0]), "r"(b[1]));
}
__device__ __forceinline__ void ldmx4t(uint32_t r[4], uint32_t addr) {
    asm volatile("ldmatrix.sync.aligned.m8n8.x4.trans.shared.b16 {%0,%1,%2,%3}, [%4];"
        : "=r"(r[0]), "=r"(r[1]), "=r"(r[2]), "=r"(r[3]) : "r"(addr));
}
__device__ __forceinline__ void cp16(uint32_t sdst, const void* gsrc) {
    asm volatile("cp.async.cg.shared.global [%0], [%1], 16;" :: "r"(sdst), "l"(gsrc));
}
#define CP_COMMIT() asm volatile("cp.async.commit_group;" ::: "memory")
#define CP_WAIT1()  asm volatile("cp.async.wait_group 1;" ::: "memory")
#define CP_WAIT0()  asm volatile("cp.async.wait_group 0;" ::: "memory")

// =======================================================================
// pack kernel: fp32 -> fp16 for X (3x) and W (4x)
// =======================================================================
#define X4 (L * DM / 4)
#define W4 (DM * DM / 4)
#define PACK_TOTAL (3 * X4 + 4 * W4)
#define PACK_BLOCKS (PACK_TOTAL / 256)

__global__ void __launch_bounds__(256)
pack_kernel(const float* __restrict__ xq, const float* __restrict__ xk, const float* __restrict__ xv,
            const float* __restrict__ wq, const float* __restrict__ wk, const float* __restrict__ wv,
            const float* __restrict__ wo)
{
    const int idx = blockIdx.x * 256 + threadIdx.x;
    float4 v;
    __half* dst;
    if (idx < 3 * X4) {
        const int z = idx / X4;
        const int r = idx - z * X4;
        const float* s = (z == 0) ? xq : (z == 1) ? xk : xv;
        v = ((const float4*)s)[r];
        dst = &g_Xh[z][r * 4];
    } else {
        const int t = idx - 3 * X4;
        const int z = t / W4;
        const int r = t - z * W4;
        const float* s = (z == 0) ? wq : (z == 1) ? wk : (z == 2) ? wv : wo;
        v = ((const float4*)s)[r];
        dst = &g_Wh[z][r * 4];
    }
    uint2 u = {f2h2(v.x, v.y), f2h2(v.z, v.w)};
    *(uint2*)dst = u;
}

// =======================================================================
// common GEMM pieces
// =======================================================================
#define BKH 64
#define SSH 72
#define NT (DM / BKH)                          // 12

// qkv: CTA tile 256x128, warp tile 64x64 (8 warps 4x2), 3-stage ring
#define QKV_STAGEH ((256 + 128) * SSH)
#define QKV_SMEM (3 * QKV_STAGEH * 2)          // 165888 B

// out_proj: CTA tile 128x192, warp tile 32x96, 3-stage ring, 1 CTA/SM
#define OUT_STAGEH ((128 + 192) * SSH)
#define OUT_SMEM (3 * OUT_STAGEH * 2)          // 138240 B

template <int MROWS, int NROWS>
__device__ __forceinline__ void stage_tiles(uint32_t sbase,
                                            const __half* __restrict__ A, int i0,
                                            const __half* __restrict__ B, int j0,
                                            int kt, int tid)
{
#pragma unroll
    for (int i = 0; i < MROWS * 8 / 256; ++i) {
        const int f = tid + i * 256;
        const int r = f >> 3, c = f & 7;
        cp16(sbase + (uint32_t)(r * SSH + c * 8) * 2,
             A + (size_t)(i0 + r) * DM + kt * BKH + c * 8);
    }
#pragma unroll
    for (int i = 0; i < NROWS * 8 / 256; ++i) {
        const int f = tid + i * 256;
        const int r = f >> 3, c = f & 7;
        cp16(sbase + (uint32_t)((MROWS + r) * SSH + c * 8) * 2,
             B + (size_t)(j0 + r) * DM + kt * BKH + c * 8);
    }
}

// =======================================================================
// qkv: fat warp tile 64x64 (R15)
// =======================================================================
__global__ void __launch_bounds__(256, 1)
qkv_proj_kernel(const float* __restrict__ bq, const float* __restrict__ bk,
                const float* __restrict__ bv)
{
    const int z = blockIdx.z;
    const float* bias = (z == 0) ? bq : (z == 1) ? bk : bv;
    __half* dst       = (z == 0) ? g_Qh : (z == 1) ? g_Kh : g_Vh;
    const float sc    = (z == 0) ? ATTN_SCALE : 1.0f;
    const __half* A   = g_Xh[z];
    const __half* B   = g_Wh[z];
    const int i0 = blockIdx.x * 256;
    const int j0 = blockIdx.y * 128;

    extern __shared__ __half smh[];
    const uint32_t sb = (uint32_t)__cvta_generic_to_shared(smh);

    const int tid  = threadIdx.x;
    const int wid  = tid >> 5;
    const int lane = tid & 31;
    const int gq   = lane >> 2;
    const int tg   = lane & 3;
    const int wm0  = (wid & 3) * 64;
    const int wn0  = (wid >> 2) * 64;

    float acc[4][8][4] = {};

    stage_tiles<256, 128>(sb, A, i0, B, j0, 0, tid);
    CP_COMMIT();
    stage_tiles<256, 128>(sb + QKV_STAGEH * 2, A, i0, B, j0, 1, tid);
    CP_COMMIT();

    int buf = 0;
    for (int kt = 0; kt < NT; ++kt) {
        if (kt == NT - 1) { CP_WAIT0(); } else { CP_WAIT1(); }
        __syncthreads();

        const __half* Ac = smh + buf * QKV_STAGEH;
        const __half* Bc = Ac + 256 * SSH;
#pragma unroll
        for (int kk = 0; kk < BKH; kk += 16) {
            uint32_t af[4][4], bf[8][2];
#pragma unroll
            for (int mt = 0; mt < 4; ++mt) {
                const int r = wm0 + mt * 16 + gq;
                af[mt][0] = *(const uint32_t*)&Ac[(r    ) * SSH + kk + 2 * tg    ];
                af[mt][1] = *(const uint32_t*)&Ac[(r + 8) * SSH + kk + 2 * tg    ];
                af[mt][2] = *(const uint32_t*)&Ac[(r    ) * SSH + kk + 2 * tg + 8];
                af[mt][3] = *(const uint32_t*)&Ac[(r + 8) * SSH + kk + 2 * tg + 8];
            }
#pragma unroll
            for (int nt = 0; nt < 8; ++nt) {
                const int n = wn0 + nt * 8 + gq;
                bf[nt][0] = *(const uint32_t*)&Bc[n * SSH + kk + 2 * tg    ];
                bf[nt][1] = *(const uint32_t*)&Bc[n * SSH + kk + 2 * tg + 8];
            }
#pragma unroll
            for (int mt = 0; mt < 4; ++mt)
#pragma unroll
                for (int nt = 0; nt < 8; ++nt)
                    mma_f16(acc[mt][nt], af[mt], bf[nt]);
        }

        if (kt + 2 < NT) {
            const int nb = (buf + 2 >= 3) ? buf - 1 : buf + 2;
            stage_tiles<256, 128>(sb + (uint32_t)nb * QKV_STAGEH * 2, A, i0, B, j0, kt + 2, tid);
            CP_COMMIT();
        }
        buf = (buf + 1 == 3) ? 0 : buf + 1;
    }

#pragma unroll
    for (int nt = 0; nt < 8; ++nt) {
        const int col = j0 + wn0 + nt * 8 + 2 * tg;
        const float2 bb = *(const float2*)&bias[col];
#pragma unroll
        for (int mt = 0; mt < 4; ++mt) {
            const int r = i0 + wm0 + mt * 16 + gq;
            uint32_t h0 = f2h2((acc[mt][nt][0] + bb.x) * sc,
                               (acc[mt][nt][1] + bb.y) * sc);
            uint32_t h1 = f2h2((acc[mt][nt][2] + bb.x) * sc,
                               (acc[mt][nt][3] + bb.y) * sc);
            *(uint32_t*)&dst[(size_t)r * DM + col] = h0;
            *(uint32_t*)&dst[(size_t)(r + 8) * DM + col] = h1;
        }
    }
}

// =======================================================================
// out_proj: 128x192 tile, 128 CTAs total -> 1 CTA/SM, single wave
// =======================================================================
__global__ void __launch_bounds__(256, 1)
out_proj_kernel(const float* __restrict__ bo, float* __restrict__ out)
{
    const int i0 = blockIdx.x * 128;          // 32
    const int j0 = blockIdx.y * 192;          // 4
    const __half* A = g_Ah;
    const __half* B = g_Wh[3];

    extern __shared__ __half smh[];
    const uint32_t sb = (uint32_t)__cvta_generic_to_shared(smh);

    const int tid  = threadIdx.x;
    const int wid  = tid >> 5;
    const int lane = tid & 31;
    const int gq   = lane >> 2;
    const int tg   = lane & 3;
    const int wm0  = (wid & 3) * 32;          // warp M base
    const int wn0  = (wid >> 2) * 96;         // warp N base (0, 96)

    float acc[2][12][4] = {};

    stage_tiles<128, 192>(sb, A, i0, B, j0, 0, tid);
    CP_COMMIT();
    stage_tiles<128, 192>(sb + OUT_STAGEH * 2, A, i0, B, j0, 1, tid);
    CP_COMMIT();

    int buf = 0;
    for (int kt = 0; kt < NT; ++kt) {
        if (kt == NT - 1) { CP_WAIT0(); } else { CP_WAIT1(); }
        __syncthreads();

        const __half* Ac = smh + buf * OUT_STAGEH;
        const __half* Bc = Ac + 128 * SSH;
#pragma unroll
        for (int kk = 0; kk < BKH; kk += 16) {
            uint32_t af[2][4], bf[12][2];
#pragma unroll
            for (int mt = 0; mt < 2; ++mt) {
                const int r = wm0 + mt * 16 + gq;
                af[mt][0] = *(const uint32_t*)&Ac[(r    ) * SSH + kk + 2 * tg    ];
                af[mt][1] = *(const uint32_t*)&Ac[(r + 8) * SSH + kk + 2 * tg    ];
                af[mt][2] = *(const uint32_t*)&Ac[(r    ) * SSH + kk + 2 * tg + 8];
                af[mt][3] = *(const uint32_t*)&Ac[(r + 8) * SSH + kk + 2 * tg + 8];
            }
#pragma unroll
            for (int nt = 0; nt < 12; ++nt) {
                const int n = wn0 + nt * 8 + gq;
                bf[nt][0] = *(const uint32_t*)&Bc[n * SSH + kk + 2 * tg    ];
                bf[nt][1] = *(const uint32_t*)&Bc[n * SSH + kk + 2 * tg + 8];
            }
#pragma unroll
            for (int mt = 0; mt < 2; ++mt)
#pragma unroll
                for (int nt = 0; nt < 12; ++nt)
                    mma_f16(acc[mt][nt], af[mt], bf[nt]);
        }

        if (kt + 2 < NT) {
            const int nb = (buf + 2 >= 3) ? buf - 1 : buf + 2;
            stage_tiles<128, 192>(sb + (uint32_t)nb * OUT_STAGEH * 2, A, i0, B, j0, kt + 2, tid);
            CP_COMMIT();
        }
        buf = (buf + 1 == 3) ? 0 : buf + 1;
    }

#pragma unroll
    for (int nt = 0; nt < 12; ++nt) {
        const int col = j0 + wn0 + nt * 8 + 2 * tg;
        const float2 bb = *(const float2*)&bo[col];
#pragma unroll
        for (int mt = 0; mt < 2; ++mt) {
            const int r = i0 + wm0 + mt * 16 + gq;
            float2 s0 = {acc[mt][nt][0] + bb.x, acc[mt][nt][1] + bb.y};
            float2 s1 = {acc[mt][nt][2] + bb.x, acc[mt][nt][3] + bb.y};
            *(float2*)&out[(size_t)r * DM + col] = s0;
            *(float2*)&out[(size_t)(r + 8) * DM + col] = s1;
        }
    }
}

// =======================================================================
// flash-style sliding-window attention (R12, unchanged)
// =======================================================================
#define AQKH 72
#define AOFF_QS 0
#define AOFF_KS 18432
#define AOFF_VS 55296
#define ATT_SMEM_BYTES (AOFF_VS + 256 * AQKH * 2)   // 92160

__global__ void __launch_bounds__(256, 2)
attn_kernel()
{
    extern __shared__ char smc[];
    __half* Qs = (__half*)(smc + AOFF_QS);
    __half* Ks = (__half*)(smc + AOFF_KS);

    const int tid  = threadIdx.x;
    const int q0   = blockIdx.x * 128;
    const int h    = blockIdx.y;
    const int c0   = h * HD;
    const int wid  = tid >> 5;
    const int lane = tid & 31;
    const int gq   = lane >> 2;
    const int tg   = lane & 3;

    const uint32_t sbase = (uint32_t)__cvta_generic_to_shared(smc);

    {
        const uint32_t sQ = sbase + AOFF_QS;
        const uint32_t sK = sbase + AOFF_KS;
        const uint32_t sV = sbase + AOFF_VS;
#pragma unroll
        for (int i = 0; i < 4; ++i) {
            const int f = tid + i * 256;
            const int q = f >> 3, c = f & 7;
            cp16(sQ + (uint32_t)(q * AQKH + c * 8) * 2,
                 g_Qh + (size_t)(q0 + q) * DM + c0 + c * 8);
        }
#pragma unroll
        for (int i = 0; i < 8; ++i) {
            const int f = tid + i * 256;
            const int j = f >> 3, c = f & 7;
            const int jg = min(max(q0 - 64 + j, 0), L - 1);
            cp16(sK + (uint32_t)(j * AQKH + c * 8) * 2,
                 g_Kh + (size_t)jg * DM + c0 + c * 8);
            cp16(sV + (uint32_t)(j * AQKH + c * 8) * 2,
                 g_Vh + (size_t)jg * DM + c0 + c * 8);
        }
        CP_COMMIT();
    }
    CP_WAIT0();
    __syncthreads();

    const int wm  = wid * 16;
    const int iq0 = q0 + wm + gq;
    const int iq1 = iq0 + 8;
    const int lo0 = max(iq0 - 64, 0), hi0 = min(iq0 + 64, L - 1);
    const int lo1 = max(iq1 - 64, 0), hi1 = min(iq1 + 64, L - 1);

    float oacc[8][4] = {};
    float m0 = -1e30f, m1 = -1e30f;
    float l0 = 0.f,    l1 = 0.f;

    const int jbase0 = (wid >> 2) * 64;
    const int vrow = lane & 15;
    const int vcol = (lane >> 4) * 8;

    for (int cb = 0; cb < 3; ++cb) {
        const int jb = jbase0 + cb * 64;

        float sc[8][4] = {};
#pragma unroll
        for (int kk = 0; kk < 64; kk += 16) {
            uint32_t a[4];
            a[0] = *(const uint32_t*)&Qs[(wm + gq    ) * AQKH + kk + 2 * tg    ];
            a[1] = *(const uint32_t*)&Qs[(wm + gq + 8) * AQKH + kk + 2 * tg    ];
            a[2] = *(const uint32_t*)&Qs[(wm + gq    ) * AQKH + kk + 2 * tg + 8];
            a[3] = *(const uint32_t*)&Qs[(wm + gq + 8) * AQKH + kk + 2 * tg + 8];
#pragma unroll
            for (int nt = 0; nt < 8; ++nt) {
                const int n = jb + nt * 8 + gq;
                uint32_t b[2];
                b[0] = *(const uint32_t*)&Ks[n * AQKH + kk + 2 * tg    ];
                b[1] = *(const uint32_t*)&Ks[n * AQKH + kk + 2 * tg + 8];
                mma_f16(sc[nt], a, b);
            }
        }

        float mn0 = m0, mn1 = m1;
#pragma unroll
        for (int nt = 0; nt < 8; ++nt) {
            const int jg0 = q0 - 64 + jb + nt * 8 + 2 * tg;
#pragma unroll
            for (int e = 0; e < 4; ++e) {
                const int jg = jg0 + (e & 1);
                float s = sc[nt][e];
                if (e < 2) {
                    s = (jg >= lo0 && jg <= hi0) ? s : -1e30f;
                    mn0 = fmaxf(mn0, s);
                } else {
                    s = (jg >= lo1 && jg <= hi1) ? s : -1e30f;
                    mn1 = fmaxf(mn1, s);
                }
                sc[nt][e] = s;
            }
        }
        mn0 = fmaxf(mn0, __shfl_xor_sync(0xffffffffu, mn0, 1));
        mn0 = fmaxf(mn0, __shfl_xor_sync(0xffffffffu, mn0, 2));
        mn1 = fmaxf(mn1, __shfl_xor_sync(0xffffffffu, mn1, 1));
        mn1 = fmaxf(mn1, __shfl_xor_sync(0xffffffffu, mn1, 2));
        const float al0 = __expf(m0 - mn0);
        const float al1 = __expf(m1 - mn1);
        m0 = mn0; m1 = mn1;

        uint32_t ph[8][2];
        float cs0 = 0.f, cs1 = 0.f;
#pragma unroll
        for (int nt = 0; nt < 8; ++nt) {
            const float p0 = __expf(sc[nt][0] - m0);
            const float p1 = __expf(sc[nt][1] - m0);
            const float p2 = __expf(sc[nt][2] - m1);
            const float p3 = __expf(sc[nt][3] - m1);
            ph[nt][0] = f2h2(p0, p1);
            ph[nt][1] = f2h2(p2, p3);
            cs0 += p0 + p1;
            cs1 += p2 + p3;
        }
        cs0 += __shfl_xor_sync(0xffffffffu, cs0, 1);
        cs0 += __shfl_xor_sync(0xffffffffu, cs0, 2);
        cs1 += __shfl_xor_sync(0xffffffffu, cs1, 1);
        cs1 += __shfl_xor_sync(0xffffffffu, cs1, 2);
        l0 = l0 * al0 + cs0;
        l1 = l1 * al1 + cs1;

#pragma unroll
        for (int dnt = 0; dnt < 8; ++dnt) {
            oacc[dnt][0] *= al0; oacc[dnt][1] *= al0;
            oacc[dnt][2] *= al1; oacc[dnt][3] *= al1;
        }

#pragma unroll
        for (int t = 0; t < 4; ++t) {
            uint32_t a[4] = { ph[2 * t][0], ph[2 * t][1],
                              ph[2 * t + 1][0], ph[2 * t + 1][1] };
#pragma unroll
            for (int dt = 0; dt < 4; ++dt) {
                uint32_t bt[4];
                ldmx4t(bt, sbase + AOFF_VS +
                       (uint32_t)((jb + t * 16 + vrow) * AQKH + dt * 16 + vcol) * 2);
                mma_f16(oacc[2 * dt    ], a, &bt[0]);
                mma_f16(oacc[2 * dt + 1], a, &bt[2]);
            }
        }
    }

    const float inv0 = 1.f / l0;
    const float inv1 = 1.f / l1;
#pragma unroll
    for (int dnt = 0; dnt < 8; ++dnt) {
        const int d = dnt * 8 + 2 * tg;
        const uint32_t h0 = f2h2(oacc[dnt][0] * inv0, oacc[dnt][1] * inv0);
        const uint32_t h1 = f2h2(oacc[dnt][2] * inv1, oacc[dnt][3] * inv1);
        *(uint32_t*)&g_Ah[(size_t)iq0 * DM + c0 + d] = h0;
        *(uint32_t*)&g_Ah[(size_t)iq1 * DM + c0 + d] = h1;
    }
}

// ---------------- launch ----------------
extern "C" void kernel_launch(void* const* d_in, const int* in_sizes, int n_in,
                              void* d_out, int out_size)
{
    const float* q  = (const float*)d_in[0];
    const float* k  = (const float*)d_in[1];
    const float* v  = (const float*)d_in[2];
    const float* Wq = (const float*)d_in[3];
    const float* bq = (const float*)d_in[4];
    const float* Wk = (const float*)d_in[5];
    const float* bk = (const float*)d_in[6];
    const float* Wv = (const float*)d_in[7];
    const float* bv = (const float*)d_in[8];
    const float* Wo = (const float*)d_in[9];
    const float* bo = (const float*)d_in[10];
    float* out = (float*)d_out;

    cudaFuncSetAttribute(qkv_proj_kernel,
                         cudaFuncAttributeMaxDynamicSharedMemorySize, QKV_SMEM);
    cudaFuncSetAttribute(out_proj_kernel,
                         cudaFuncAttributeMaxDynamicSharedMemorySize, OUT_SMEM);
    cudaFuncSetAttribute(attn_kernel,
                         cudaFuncAttributeMaxDynamicSharedMemorySize, ATT_SMEM_BYTES);

    pack_kernel<<<PACK_BLOCKS, 256>>>(q, k, v, Wq, Wk, Wv, Wo);
    qkv_proj_kernel<<<dim3(L / 256, DM / 128, 3), 256, QKV_SMEM>>>(bq, bk, bv);
    attn_kernel<<<dim3(L / 128, NH), 256, ATT_SMEM_BYTES>>>();
    out_proj_kernel<<<dim3(L / 128, DM / 192), 256, OUT_SMEM>>>(bo, out);
}